// round 1
// baseline (speedup 1.0000x reference)
#include <cuda_runtime.h>
#include <cuda_bf16.h>
#include <math.h>

// Problem constants
#define CIN   64
#define COUT  256
#define DD    31
#define HH    96
#define WW    96
#define HW    (HH*WW)           // 9216
#define DHW   (DD*HW)           // 285696
#define EPS   1e-5f

// Tiling
#define TILE_H     16
#define TILE_W     16
#define COUT_TILE  32
#define CIN_CHUNK  8
#define THREADS    256

// smem partition sizes (floats)
#define SX_ELEMS (CIN_CHUNK*3*18*18)         // 7776
#define SW_ELEMS (COUT_TILE*CIN_CHUNK*27)    // 6912
#define SMEM_BYTES ((SX_ELEMS + SW_ELEMS)*4) // 58752

// Activated gate scratch: [256][31][96][96] floats = 292.5 MB
__device__ float g_gates[(size_t)COUT * DHW];

__device__ __forceinline__ float sigmoidf_(float v) {
    return 1.0f / (1.0f + expf(-v));
}

__global__ __launch_bounds__(THREADS, 2)
void conv_bn_act_kernel(const float* __restrict__ x,
                        const float* __restrict__ w,
                        const float* __restrict__ gamma,
                        const float* __restrict__ beta,
                        const float* __restrict__ mean,
                        const float* __restrict__ var)
{
    extern __shared__ float smem[];
    float* sx = smem;              // [CIN_CHUNK][3][18][18]
    float* sw = smem + SX_ELEMS;   // [COUT_TILE][CIN_CHUNK][27]

    const int tid   = threadIdx.x;
    const int bz    = blockIdx.z;
    const int d     = bz % DD;                 // output depth slice
    const int coutBase = (bz / DD) * COUT_TILE;
    const int hBase = blockIdx.y * TILE_H;
    const int wBase = blockIdx.x * TILE_W;

    // thread tile: 8 couts x 4 w-consecutive spatial points
    const int cog = tid >> 6;          // 0..3 -> cout subgroup of 8
    const int sid = tid & 63;          // 0..63 spatial slot
    const int hl  = sid >> 2;          // 0..15 local h
    const int w0  = (sid & 3) * 4;     // 0,4,8,12 local w base

    float acc[8][4];
#pragma unroll
    for (int a = 0; a < 8; ++a)
#pragma unroll
        for (int j = 0; j < 4; ++j) acc[a][j] = 0.0f;

    for (int cinBase = 0; cinBase < CIN; cinBase += CIN_CHUNK) {
        // ---- stage x tile: [CIN_CHUNK][d-1..d+1][hBase-1..+16][wBase-1..+16]
        for (int i = tid; i < SX_ELEMS; i += THREADS) {
            int t = i;
            const int lw = t % 18; t /= 18;
            const int lh = t % 18; t /= 18;
            const int dz = t % 3;  t /= 3;
            const int ci = t;
            const int gw = wBase + lw - 1;
            const int gh = hBase + lh - 1;
            const int gd = d + dz - 1;
            float v = 0.0f;
            if ((unsigned)gw < WW && (unsigned)gh < HH && (unsigned)gd < DD) {
                v = x[(size_t)(cinBase + ci) * DHW + (size_t)gd * HW + gh * WW + gw];
            }
            sx[i] = v;
        }
        // ---- stage weights: [COUT_TILE][CIN_CHUNK][27]
        for (int i = tid; i < SW_ELEMS; i += THREADS) {
            int t = i;
            const int tap = t % 27; t /= 27;
            const int ci  = t % CIN_CHUNK; t /= CIN_CHUNK;
            const int co  = t;
            sw[i] = w[((size_t)(coutBase + co) * CIN + (cinBase + ci)) * 27 + tap];
        }
        __syncthreads();

        // ---- compute
        for (int cc = 0; cc < CIN_CHUNK; ++cc) {
            const float* sxc = sx + cc * (3 * 18 * 18);
            const float* swc = sw + (cog * 8) * (CIN_CHUNK * 27) + cc * 27;
#pragma unroll
            for (int kd = 0; kd < 3; ++kd) {
#pragma unroll
                for (int kh = 0; kh < 3; ++kh) {
#pragma unroll
                    for (int kw = 0; kw < 3; ++kw) {
                        const int tap = (kd * 3 + kh) * 3 + kw;
                        const float* row = sxc + (kd * 18 + (hl + kh)) * 18 + (w0 + kw);
                        float xv0 = row[0], xv1 = row[1], xv2 = row[2], xv3 = row[3];
#pragma unroll
                        for (int co = 0; co < 8; ++co) {
                            const float wv = swc[co * (CIN_CHUNK * 27) + tap];
                            acc[co][0] = fmaf(wv, xv0, acc[co][0]);
                            acc[co][1] = fmaf(wv, xv1, acc[co][1]);
                            acc[co][2] = fmaf(wv, xv2, acc[co][2]);
                            acc[co][3] = fmaf(wv, xv3, acc[co][3]);
                        }
                    }
                }
            }
        }
        __syncthreads();
    }

    // ---- BN + activation epilogue, write activated gates to scratch
    const int gh = hBase + hl;
#pragma unroll
    for (int co = 0; co < 8; ++co) {
        const int cout = coutBase + cog * 8 + co;
        const float sc = gamma[cout] * rsqrtf(var[cout] + EPS);
        const float sh = beta[cout] - mean[cout] * sc;
        const int gate = cout >> 6;          // 0:tanh 1:sig 2:sig 3:tanh
        float* dst = g_gates + (size_t)cout * DHW + (size_t)d * HW + gh * WW + (wBase + w0);
#pragma unroll
        for (int j = 0; j < 4; ++j) {
            float v = acc[co][j] * sc + sh;
            v = (gate == 1 || gate == 2) ? sigmoidf_(v) : tanhf(v);
            dst[j] = v;
        }
    }
}

// One thread per (c, h, w); serial scan over d.
__global__ void sru_scan_kernel(float* __restrict__ out)
{
    const int idx = blockIdx.x * blockDim.x + threadIdx.x;
    if (idx >= CIN * HW) return;
    const int c  = idx / HW;
    const int hw = idx % HW;

    const float* pw = g_gates + (size_t)(0 * 64 + c) * DHW + hw;   // tanh(Wx)
    const float* pf = g_gates + (size_t)(1 * 64 + c) * DHW + hw;   // sigmoid(f)
    const float* pr = g_gates + (size_t)(2 * 64 + c) * DHW + hw;   // sigmoid(r)
    const float* px = g_gates + (size_t)(3 * 64 + c) * DHW + hw;   // tanh(X)
    float* po = out + (size_t)c * DHW + hw;

    // t = 0: Ct = 1 - f  (Wx unused)
    float f = pf[0];
    float r = pr[0];
    float xx = px[0];
    float C = 1.0f - f;
    po[0] = r * C + (1.0f - r) * xx;

    for (int d = 1; d < DD; ++d) {
        const int off = d * HW;
        const float wv = pw[off];
        f  = pf[off];
        r  = pr[off];
        xx = px[off];
        C = f * C + (1.0f - f) * wv;
        po[off] = r * C + (1.0f - r) * xx;
    }
}

extern "C" void kernel_launch(void* const* d_in, const int* in_sizes, int n_in,
                              void* d_out, int out_size)
{
    const float* x     = (const float*)d_in[0];
    const float* w     = (const float*)d_in[1];
    const float* gamma = (const float*)d_in[2];
    const float* beta  = (const float*)d_in[3];
    const float* mean  = (const float*)d_in[4];
    const float* var   = (const float*)d_in[5];
    float* out = (float*)d_out;

    cudaFuncSetAttribute(conv_bn_act_kernel,
                         cudaFuncAttributeMaxDynamicSharedMemorySize, SMEM_BYTES);

    dim3 grid(WW / TILE_W, HH / TILE_H, DD * (COUT / COUT_TILE)); // 6 x 6 x 248
    conv_bn_act_kernel<<<grid, THREADS, SMEM_BYTES>>>(x, w, gamma, beta, mean, var);

    const int scan_threads = 256;
    const int scan_blocks = (CIN * HW + scan_threads - 1) / scan_threads;
    sru_scan_kernel<<<scan_blocks, scan_threads>>>(out);
}

// round 3
// speedup vs baseline: 3.2603x; 3.2603x over previous
#include <cuda_runtime.h>
#include <cstdint>
#include <math.h>

#define CIN 64
#define COUT 256
#define DD 31
#define HH 96
#define WW 96
#define HW (HH*WW)
#define DHW (DD*HW)
#define EPS 1e-5f

#define A_STRIDE 132   // 128 couts + 4 pad (words); rows = 32 k
#define B_STRIDE 36    // 32 k + 4 pad (words); rows = 128 n

__device__ float g_gates[(size_t)COUT * DHW];   // activated gates [cout][d][h][w]
__device__ float g_wt2[27 * CIN * COUT];        // [tap][ci][cout], tf32-rounded bits

__device__ __forceinline__ uint32_t cvta_s(const void* p) {
    uint32_t a;
    asm("{ .reg .u64 t; cvta.to.shared.u64 t, %1; cvt.u32.u64 %0, t; }" : "=r"(a) : "l"(p));
    return a;
}
__device__ __forceinline__ float fast_tanh(float x) {
    float y; asm("tanh.approx.f32 %0, %1;" : "=f"(y) : "f"(x)); return y;
}
__device__ __forceinline__ uint32_t to_tf32(float v) {
    uint32_t u; asm("cvt.rna.tf32.f32 %0, %1;" : "=r"(u) : "f"(v)); return u;
}

// w[cout][cin][27] -> g_wt2[tap][cin][cout] (tf32-rounded)
__global__ void repack_kernel(const float* __restrict__ w) {
    int id = blockIdx.x * blockDim.x + threadIdx.x;
    if (id >= COUT * CIN) return;
    int cout = id >> 6, cin = id & 63;
    const float* src = w + (size_t)id * 27;
    uint32_t* dst = (uint32_t*)g_wt2;
#pragma unroll
    for (int t = 0; t < 27; ++t)
        dst[(t * CIN + cin) * COUT + cout] = to_tf32(src[t]);
}

__global__ __launch_bounds__(128, 2)
void conv_mma_kernel(const float* __restrict__ x,
                     const float* __restrict__ gamma, const float* __restrict__ beta,
                     const float* __restrict__ mean, const float* __restrict__ var)
{
    __shared__ float smA[32 * A_STRIDE];    // [k][co]  16.9 KB
    __shared__ float smB[128 * B_STRIDE];   // [n][k]   18.4 KB
    const int tid = threadIdx.x, wid = tid >> 5, lane = tid & 31;
    const int d = blockIdx.y;
    const int coutBase = blockIdx.z * 128;
    const int hBase = (blockIdx.x / 3) * 4, wBase = (blockIdx.x % 3) * 32;
    const uint32_t smA_u = cvta_s(smA), smB_u = cvta_s(smB);

    // B staging: this thread owns spatial point n = tid
    const int nB = tid;
    const int hl = nB >> 5, wl = nB & 31;

    float acc[4][8][4];
#pragma unroll
    for (int f = 0; f < 4; ++f)
#pragma unroll
        for (int g = 0; g < 8; ++g)
#pragma unroll
            for (int c = 0; c < 4; ++c) acc[f][g][c] = 0.0f;

    const int warpM = (wid >> 1) * 64, warpN = (wid & 1) * 64;
    const int mr = lane >> 2, nc = lane & 3;

    for (int kd = 0; kd < 3; ++kd) {
        const int dz = d + kd - 1;
        if ((unsigned)dz >= DD) continue;
        for (int kh = 0; kh < 3; ++kh) {
            const int hg = hBase + hl + kh - 1;
            for (int kw = 0; kw < 3; ++kw) {
                const int wg = wBase + wl + kw - 1;
                const bool ok = ((unsigned)hg < HH) && ((unsigned)wg < WW);
                const int tap = (kd * 3 + kh) * 3 + kw;
                const float* xs = x + (size_t)dz * HW + hg * WW + wg;
                for (int ch = 0; ch < 2; ++ch) {
                    const int ci0 = ch * 32;
                    __syncthreads();   // previous compute done; smem reusable
                    // ---- stage A (weights) via cp.async: smA[k][co]
                    {
                        const char* asrc = (const char*)(g_wt2
                            + (size_t)(tap * 64 + ci0) * 256 + coutBase);
#pragma unroll
                        for (int c = 0; c < 8; ++c) {
                            int idx = tid * 8 + c;          // 0..1023 16B chunks
                            int ci = idx >> 5, co16 = idx & 31;
                            uint32_t dsta = smA_u + ci * (A_STRIDE * 4) + co16 * 16;
                            asm volatile("cp.async.cg.shared.global [%0], [%1], 16;"
                                         :: "r"(dsta), "l"(asrc + ci * 1024 + co16 * 16));
                        }
                        asm volatile("cp.async.commit_group;" ::: "memory");
                    }
                    // ---- stage B (x gather, transpose to [n][k]) in 2 halves
#pragma unroll
                    for (int h2 = 0; h2 < 2; ++h2) {
                        uint32_t uv[16];
#pragma unroll
                        for (int j = 0; j < 16; ++j) {
                            float v = ok ? xs[(size_t)(ci0 + h2 * 16 + j) * DHW] : 0.0f;
                            uv[j] = to_tf32(v);
                        }
#pragma unroll
                        for (int q = 0; q < 4; ++q) {
                            uint32_t addr = smB_u + nB * (B_STRIDE * 4) + (h2 * 16 + q * 4) * 4;
                            asm volatile("st.shared.v4.b32 [%0], {%1,%2,%3,%4};"
                                :: "r"(addr), "r"(uv[q*4]), "r"(uv[q*4+1]),
                                   "r"(uv[q*4+2]), "r"(uv[q*4+3]));
                        }
                    }
                    asm volatile("cp.async.wait_group 0;" ::: "memory");
                    __syncthreads();
                    // ---- compute 4 x k8 steps
#pragma unroll
                    for (int s = 0; s < 4; ++s) {
                        const int kk = s * 8 + nc;
                        uint32_t a[4][4];
#pragma unroll
                        for (int f = 0; f < 4; ++f) {
                            const int m = warpM + 16 * f + mr;
                            a[f][0] = __float_as_uint(smA[kk * A_STRIDE + m]);
                            a[f][1] = __float_as_uint(smA[kk * A_STRIDE + m + 8]);
                            a[f][2] = __float_as_uint(smA[(kk + 4) * A_STRIDE + m]);
                            a[f][3] = __float_as_uint(smA[(kk + 4) * A_STRIDE + m + 8]);
                        }
                        uint32_t b[8][2];
#pragma unroll
                        for (int g = 0; g < 8; ++g) {
                            const int nn = warpN + 8 * g + mr;
                            b[g][0] = __float_as_uint(smB[nn * B_STRIDE + kk]);
                            b[g][1] = __float_as_uint(smB[nn * B_STRIDE + kk + 4]);
                        }
#pragma unroll
                        for (int f = 0; f < 4; ++f)
#pragma unroll
                            for (int g = 0; g < 8; ++g) {
                                asm volatile(
                                    "mma.sync.aligned.m16n8k8.row.col.f32.tf32.tf32.f32 "
                                    "{%0,%1,%2,%3}, {%4,%5,%6,%7}, {%8,%9}, {%0,%1,%2,%3};"
                                    : "+f"(acc[f][g][0]), "+f"(acc[f][g][1]),
                                      "+f"(acc[f][g][2]), "+f"(acc[f][g][3])
                                    : "r"(a[f][0]), "r"(a[f][1]), "r"(a[f][2]), "r"(a[f][3]),
                                      "r"(b[g][0]), "r"(b[g][1]));
                            }
                    }
                }
            }
        }
    }

    // ---- epilogue: BN + activation + direct STG (float2)
    float scv[8], shv[8];
#pragma unroll
    for (int f = 0; f < 4; ++f)
#pragma unroll
        for (int r = 0; r < 2; ++r) {
            const int cg = coutBase + warpM + 16 * f + 8 * r + mr;
            const float s = gamma[cg] * rsqrtf(var[cg] + EPS);
            scv[f * 2 + r] = s;
            shv[f * 2 + r] = beta[cg] - mean[cg] * s;
        }
#pragma unroll
    for (int f = 0; f < 4; ++f)
#pragma unroll
        for (int r = 0; r < 2; ++r) {
            const int cg = coutBase + warpM + 16 * f + 8 * r + mr;
            const int gt = cg >> 6;
            const bool sg = (gt == 1) || (gt == 2);
            const float s0 = scv[f * 2 + r], s1 = shv[f * 2 + r];
            float* orow = g_gates + (size_t)cg * DHW + (size_t)d * HW;
#pragma unroll
            for (int g = 0; g < 8; ++g) {
                const int n0 = warpN + 8 * g + 2 * nc;
                const int h2 = n0 >> 5, w2 = n0 & 31;
                float v0 = acc[f][g][2 * r + 0] * s0 + s1;
                float v1 = acc[f][g][2 * r + 1] * s0 + s1;
                if (sg) {
                    v0 = 0.5f * fast_tanh(0.5f * v0) + 0.5f;
                    v1 = 0.5f * fast_tanh(0.5f * v1) + 0.5f;
                } else {
                    v0 = fast_tanh(v0);
                    v1 = fast_tanh(v1);
                }
                *reinterpret_cast<float2*>(orow + (hBase + h2) * WW + wBase + w2)
                    = make_float2(v0, v1);
            }
        }
}

// ---------------- SRU scan over depth ----------------
__global__ void sru_scan_kernel(float* __restrict__ out)
{
    const int idx = blockIdx.x * blockDim.x + threadIdx.x;
    if (idx >= CIN * HW) return;
    const int c = idx / HW;
    const int hw = idx % HW;

    const float* pw = g_gates + (size_t)(0 * 64 + c) * DHW + hw;
    const float* pf = g_gates + (size_t)(1 * 64 + c) * DHW + hw;
    const float* pr = g_gates + (size_t)(2 * 64 + c) * DHW + hw;
    const float* px = g_gates + (size_t)(3 * 64 + c) * DHW + hw;
    float* po = out + (size_t)c * DHW + hw;

    float f = pf[0], r = pr[0], xx = px[0];
    float C = 1.0f - f;
    po[0] = r * C + (1.0f - r) * xx;

    for (int dd = 1; dd < DD; ++dd) {
        const int off = dd * HW;
        const float wv = pw[off];
        f = pf[off]; r = pr[off]; xx = px[off];
        C = f * C + (1.0f - f) * wv;
        po[off] = r * C + (1.0f - r) * xx;
    }
}

extern "C" void kernel_launch(void* const* d_in, const int* in_sizes, int n_in,
                              void* d_out, int out_size)
{
    const float* x     = (const float*)d_in[0];
    const float* w     = (const float*)d_in[1];
    const float* gamma = (const float*)d_in[2];
    const float* beta  = (const float*)d_in[3];
    const float* mean  = (const float*)d_in[4];
    const float* var   = (const float*)d_in[5];
    float* out = (float*)d_out;

    repack_kernel<<<64, 256>>>(w);

    dim3 grid(72, 31, 2);    // (h-tiles x w-tiles), d, cout-groups
    conv_mma_kernel<<<grid, 128>>>(x, gamma, beta, mean, var);

    const int scan_threads = 256;
    const int scan_blocks = (CIN * HW + scan_threads - 1) / scan_threads;
    sru_scan_kernel<<<scan_blocks, scan_threads>>>(out);
}

// round 4
// speedup vs baseline: 6.1173x; 1.8763x over previous
#include <cuda_runtime.h>
#include <cuda_fp16.h>
#include <cstdint>
#include <math.h>

#define CIN 64
#define COUT 256
#define DD 31
#define HH 96
#define WW 96
#define HW (HH*WW)
#define DHW (DD*HW)
#define EPS 1e-5f

// smem: A = 3 taps x [128 co][64 ci] fp16 (swizzled 128B rows) = 49152 B
//       B = [136 n_ext][64 ci] fp16 (swizzled)                 = 17408 B
#define SMA_TAP_BYTES 16384
#define SMB_OFF (3*SMA_TAP_BYTES)
#define SMEM_TOTAL (SMB_OFF + 136*128)    // 66560

__device__ float  g_gates[(size_t)COUT * DHW];   // activated gates [cout][d][h][w]
__device__ __half g_wth[27 * COUT * CIN];        // [tap][cout][cin] fp16

__device__ __forceinline__ uint32_t cvta_s(const void* p) {
    uint32_t a;
    asm("{ .reg .u64 t; cvta.to.shared.u64 t, %1; cvt.u32.u64 %0, t; }" : "=r"(a) : "l"(p));
    return a;
}
__device__ __forceinline__ float fast_tanh(float x) {
    float y; asm("tanh.approx.f32 %0, %1;" : "=f"(y) : "f"(x)); return y;
}
__device__ __forceinline__ void ldsm_x4(uint32_t& r0, uint32_t& r1, uint32_t& r2, uint32_t& r3,
                                        uint32_t addr) {
    asm volatile("ldmatrix.sync.aligned.m8n8.x4.shared.b16 {%0,%1,%2,%3}, [%4];"
        : "=r"(r0), "=r"(r1), "=r"(r2), "=r"(r3) : "r"(addr));
}
#define STS128_V(addr, a0, a1, a2, a3) \
    asm volatile("st.shared.v4.b32 [%0], {%1,%2,%3,%4};" \
        :: "r"(addr), "r"(a0), "r"(a1), "r"(a2), "r"(a3) : "memory")

// w[cout][cin][27] -> g_wth[tap][cout][cin]
__global__ void repack_kernel(const float* __restrict__ w) {
    int id = blockIdx.x * blockDim.x + threadIdx.x;
    if (id >= COUT * CIN) return;
    int cout = id >> 6, cin = id & 63;
    const float* src = w + (size_t)id * 27;
#pragma unroll
    for (int t = 0; t < 27; ++t)
        g_wth[((size_t)t * COUT + cout) * CIN + cin] = __float2half_rn(src[t]);
}

__global__ __launch_bounds__(128, 2)
void conv_mma_kernel(const float* __restrict__ x,
                     const float* __restrict__ gamma, const float* __restrict__ beta,
                     const float* __restrict__ mean, const float* __restrict__ var)
{
    extern __shared__ char smem[];
    const uint32_t smA_u = cvta_s(smem);
    const uint32_t smB_u = smA_u + SMB_OFF;

    const int tid = threadIdx.x, wid = tid >> 5, lane = tid & 31;
    const int d = blockIdx.y;
    const int coutBase = blockIdx.z * 128;
    const int hBase = (blockIdx.x / 3) * 4, wBase = (blockIdx.x % 3) * 32;

    const int warpM = (wid >> 1) * 64, warpN = (wid & 1) * 64;
    const int mr = lane >> 2, nc = lane & 3;

    // ldmatrix lane decomposition
    const int matsel = lane >> 3, rl = lane & 7;
    const int mhalf = matsel & 1;        // 0: low 8 rows, 1: high 8 rows
    const int khalf = matsel >> 1;       // 0: k0-7, 1: k8-15

    // per-lane A row constants for the 4 m16 tiles
    int rowA[4], rowA7[4];
#pragma unroll
    for (int f = 0; f < 4; ++f) {
        rowA[f] = warpM + 16 * f + mhalf * 8 + rl;
        rowA7[f] = rowA[f] & 7;
    }
    // per-lane B n_ext base row for the 4 n16 groups (add kw at use)
    int browB[4];
#pragma unroll
    for (int g2 = 0; g2 < 4; ++g2) {
        int n = warpN + g2 * 16 + mhalf * 8 + rl;
        browB[g2] = (n >> 5) * 34 + (n & 31);
    }

    float acc[4][8][4];
#pragma unroll
    for (int f = 0; f < 4; ++f)
#pragma unroll
        for (int g = 0; g < 8; ++g)
#pragma unroll
            for (int c = 0; c < 4; ++c) acc[f][g][c] = 0.0f;

    for (int kd = 0; kd < 3; ++kd) {
        const int dz = d + kd - 1;
        if ((unsigned)dz >= DD) continue;
        const float* xdz = x + (size_t)dz * HW;
        for (int kh = 0; kh < 3; ++kh) {
            __syncthreads();   // previous compute done; smem reusable

            // ---- stage 3 A taps via cp.async: [co row][ci], swizzled
            {
                const int row = tid;   // 128 rows
                const uint32_t sw = (uint32_t)(row & 7);
#pragma unroll
                for (int t3 = 0; t3 < 3; ++t3) {
                    const int tap = (kd * 3 + kh) * 3 + t3;
                    const char* src = (const char*)(g_wth
                        + ((size_t)tap * COUT + coutBase + row) * CIN);
                    const uint32_t dbase = smA_u + t3 * SMA_TAP_BYTES + row * 128;
#pragma unroll
                    for (int c = 0; c < 8; ++c) {
                        asm volatile("cp.async.cg.shared.global [%0], [%1], 16;"
                            :: "r"(dbase + ((c ^ sw) << 4)), "l"(src + c * 16));
                    }
                }
                asm volatile("cp.async.commit_group;" ::: "memory");
            }

            // ---- stage Bext [136 rows = 4h x 34w][64 ci] fp16, swizzled
            for (int rr = tid; rr < 136; rr += 128) {
                const int hl = rr / 34, wext = rr - hl * 34;
                const int hg = hBase + hl + kh - 1;
                const int wg = wBase + wext - 1;
                const bool ok = ((unsigned)hg < HH) && ((unsigned)wg < WW);
                const float* xp = xdz + hg * WW + wg;
                const uint32_t sw = (uint32_t)(rr & 7);
                const uint32_t dbase = smB_u + rr * 128;
#pragma unroll
                for (int c = 0; c < 8; ++c) {
                    uint32_t pk[4];
#pragma unroll
                    for (int j = 0; j < 4; ++j) {
                        const int ci = c * 8 + j * 2;
                        float v0 = ok ? xp[(size_t)ci * DHW] : 0.0f;
                        float v1 = ok ? xp[(size_t)(ci + 1) * DHW] : 0.0f;
                        __half2 h2 = __float22half2_rn(make_float2(v0, v1));
                        pk[j] = *reinterpret_cast<uint32_t*>(&h2);
                    }
                    STS128_V(dbase + ((c ^ sw) << 4), pk[0], pk[1], pk[2], pk[3]);
                }
            }
            asm volatile("cp.async.wait_group 0;" ::: "memory");
            __syncthreads();

            // ---- compute: 3 kw taps from staged A/Bext
#pragma unroll
            for (int kw = 0; kw < 3; ++kw) {
                const uint32_t Abase = smA_u + kw * SMA_TAP_BYTES;
#pragma unroll
                for (int s = 0; s < 4; ++s) {
                    const int col16 = s * 2 + khalf;
                    // A frags
                    uint32_t a[4][4];
#pragma unroll
                    for (int f = 0; f < 4; ++f) {
                        ldsm_x4(a[f][0], a[f][1], a[f][2], a[f][3],
                                Abase + rowA[f] * 128 + ((col16 ^ rowA7[f]) << 4));
                    }
                    // B frags
                    uint32_t b[8][2];
#pragma unroll
                    for (int g2 = 0; g2 < 4; ++g2) {
                        const int brow = browB[g2] + kw;
                        ldsm_x4(b[2 * g2][0], b[2 * g2 + 1][0],
                                b[2 * g2][1], b[2 * g2 + 1][1],
                                smB_u + brow * 128 + ((col16 ^ (brow & 7)) << 4));
                    }
#pragma unroll
                    for (int f = 0; f < 4; ++f)
#pragma unroll
                        for (int g = 0; g < 8; ++g) {
                            asm volatile(
                                "mma.sync.aligned.m16n8k16.row.col.f32.f16.f16.f32 "
                                "{%0,%1,%2,%3}, {%4,%5,%6,%7}, {%8,%9}, {%0,%1,%2,%3};"
                                : "+f"(acc[f][g][0]), "+f"(acc[f][g][1]),
                                  "+f"(acc[f][g][2]), "+f"(acc[f][g][3])
                                : "r"(a[f][0]), "r"(a[f][1]), "r"(a[f][2]), "r"(a[f][3]),
                                  "r"(b[g][0]), "r"(b[g][1]));
                        }
                }
            }
        }
    }

    // ---- epilogue: BN + activation + STG (float2)
#pragma unroll
    for (int f = 0; f < 4; ++f)
#pragma unroll
        for (int r = 0; r < 2; ++r) {
            const int cg = coutBase + warpM + 16 * f + 8 * r + mr;
            const float s = gamma[cg] * rsqrtf(var[cg] + EPS);
            const float sh = beta[cg] - mean[cg] * s;
            const int gt = cg >> 6;
            const bool sg = (gt == 1) || (gt == 2);
            float* orow = g_gates + (size_t)cg * DHW + (size_t)d * HW;
#pragma unroll
            for (int g = 0; g < 8; ++g) {
                const int n0 = warpN + 8 * g + 2 * nc;
                const int h2 = n0 >> 5, w2 = n0 & 31;
                float v0 = acc[f][g][2 * r + 0] * s + sh;
                float v1 = acc[f][g][2 * r + 1] * s + sh;
                if (sg) {
                    v0 = 0.5f * fast_tanh(0.5f * v0) + 0.5f;
                    v1 = 0.5f * fast_tanh(0.5f * v1) + 0.5f;
                } else {
                    v0 = fast_tanh(v0);
                    v1 = fast_tanh(v1);
                }
                *reinterpret_cast<float2*>(orow + (hBase + h2) * WW + wBase + w2)
                    = make_float2(v0, v1);
            }
        }
}

// ---------------- SRU scan over depth ----------------
__global__ void sru_scan_kernel(float* __restrict__ out)
{
    const int idx = blockIdx.x * blockDim.x + threadIdx.x;
    if (idx >= CIN * HW) return;
    const int c = idx / HW;
    const int hw = idx % HW;

    const float* pw = g_gates + (size_t)(0 * 64 + c) * DHW + hw;
    const float* pf = g_gates + (size_t)(1 * 64 + c) * DHW + hw;
    const float* pr = g_gates + (size_t)(2 * 64 + c) * DHW + hw;
    const float* px = g_gates + (size_t)(3 * 64 + c) * DHW + hw;
    float* po = out + (size_t)c * DHW + hw;

    float f = pf[0], r = pr[0], xx = px[0];
    float C = 1.0f - f;
    po[0] = r * C + (1.0f - r) * xx;

    for (int dd = 1; dd < DD; ++dd) {
        const int off = dd * HW;
        const float wv = pw[off];
        f = pf[off]; r = pr[off]; xx = px[off];
        C = f * C + (1.0f - f) * wv;
        po[off] = r * C + (1.0f - r) * xx;
    }
}

extern "C" void kernel_launch(void* const* d_in, const int* in_sizes, int n_in,
                              void* d_out, int out_size)
{
    const float* x     = (const float*)d_in[0];
    const float* w     = (const float*)d_in[1];
    const float* gamma = (const float*)d_in[2];
    const float* beta  = (const float*)d_in[3];
    const float* mean  = (const float*)d_in[4];
    const float* var   = (const float*)d_in[5];
    float* out = (float*)d_out;

    repack_kernel<<<64, 256>>>(w);

    cudaFuncSetAttribute(conv_mma_kernel,
                         cudaFuncAttributeMaxDynamicSharedMemorySize, SMEM_TOTAL);
    dim3 grid(72, 31, 2);    // (h-tiles x w-tiles), d, cout-groups
    conv_mma_kernel<<<grid, 128, SMEM_TOTAL>>>(x, gamma, beta, mean, var);

    const int scan_threads = 256;
    const int scan_blocks = (CIN * HW + scan_threads - 1) / scan_threads;
    sru_scan_kernel<<<scan_blocks, scan_threads>>>(out);
}

// round 5
// speedup vs baseline: 8.0711x; 1.3194x over previous
#include <cuda_runtime.h>
#include <cuda_fp16.h>
#include <cstdint>
#include <math.h>

#define CIN 64
#define COUT 256
#define DD 31
#define HH 96
#define WW 96
#define HW (HH*WW)
#define DHW (DD*HW)
#define EPS 1e-5f

#define BH 8
#define BW 32
#define EXT_ROWS (3*10*34)              // 1020 rows of 64 ci fp16
#define SMA_BYTES 16384                 // one A tap: 128 co x 64 ci fp16
#define SMB_OFF (2*SMA_BYTES)           // A double buffer
#define SMEM_TOTAL (SMB_OFF + EXT_ROWS*128)   // 163328

__device__ float  g_gates[(size_t)COUT * DHW];   // activated gates [cout][d][h][w]
__device__ __half g_wth[27 * COUT * CIN];        // [tap][cout][cin] fp16

__device__ __forceinline__ uint32_t cvta_s(const void* p) {
    uint32_t a;
    asm("{ .reg .u64 t; cvta.to.shared.u64 t, %1; cvt.u32.u64 %0, t; }" : "=r"(a) : "l"(p));
    return a;
}
__device__ __forceinline__ float fast_tanh(float x) {
    float y; asm("tanh.approx.f32 %0, %1;" : "=f"(y) : "f"(x)); return y;
}
__device__ __forceinline__ void ldsm_x4(uint32_t& r0, uint32_t& r1, uint32_t& r2, uint32_t& r3,
                                        uint32_t addr) {
    asm volatile("ldmatrix.sync.aligned.m8n8.x4.shared.b16 {%0,%1,%2,%3}, [%4];"
        : "=r"(r0), "=r"(r1), "=r"(r2), "=r"(r3) : "r"(addr));
}
#define STS128_V(addr, a0, a1, a2, a3) \
    asm volatile("st.shared.v4.b32 [%0], {%1,%2,%3,%4};" \
        :: "r"(addr), "r"(a0), "r"(a1), "r"(a2), "r"(a3) : "memory")

// w[cout][cin][27] -> g_wth[tap][cout][cin]
__global__ void repack_kernel(const float* __restrict__ w) {
    int id = blockIdx.x * blockDim.x + threadIdx.x;
    if (id >= COUT * CIN) return;
    int cout = id >> 6, cin = id & 63;
    const float* src = w + (size_t)id * 27;
#pragma unroll
    for (int t = 0; t < 27; ++t)
        g_wth[((size_t)t * COUT + cout) * CIN + cin] = __float2half_rn(src[t]);
}

__device__ __forceinline__ void stage_A(uint32_t smA_u, int buf, int tap,
                                        int coutBase, int tid) {
    const char* base = (const char*)(g_wth + ((size_t)tap * COUT + coutBase) * CIN);
    const uint32_t dst0 = smA_u + buf * SMA_BYTES;
#pragma unroll
    for (int c4 = 0; c4 < 4; ++c4) {
        const int idx = tid * 4 + c4;          // 0..1023 16B chunks
        const int row = idx >> 3, c = idx & 7;
        asm volatile("cp.async.cg.shared.global [%0], [%1], 16;"
            :: "r"(dst0 + row * 128 + ((c ^ (row & 7)) << 4)),
               "l"(base + row * 128 + c * 16));
    }
}

__global__ __launch_bounds__(256, 1)
void conv_mma_kernel(const float* __restrict__ x,
                     const float* __restrict__ gamma, const float* __restrict__ beta,
                     const float* __restrict__ mean, const float* __restrict__ var)
{
    extern __shared__ char smem[];
    const uint32_t smA_u = cvta_s(smem);
    const uint32_t smB_u = smA_u + SMB_OFF;

    const int tid = threadIdx.x, wid = tid >> 5, lane = tid & 31;
    const int d = blockIdx.y;
    const int coutBase = blockIdx.z * 128;
    const int hBase = (blockIdx.x / 3) * BH, wBase = (blockIdx.x % 3) * BW;

    const int warpM = (wid >> 2) * 64, warpN = (wid & 3) * 64;
    const int mr = lane >> 2, nc = lane & 3;
    const int matsel = lane >> 3, rl = lane & 7;
    const int mhalf = matsel & 1, khalf = matsel >> 1;

    int rowA[4], rowA7[4];
#pragma unroll
    for (int f = 0; f < 4; ++f) {
        rowA[f] = warpM + 16 * f + mhalf * 8 + rl;
        rowA7[f] = rowA[f] & 7;
    }
    int browB[4];
#pragma unroll
    for (int g2 = 0; g2 < 4; ++g2) {
        int n = warpN + g2 * 16 + mhalf * 8 + rl;
        browB[g2] = (n >> 5) * 34 + (n & 31);
    }

    // ---- prefetch A tap 0
    stage_A(smA_u, 0, 0, coutBase, tid);
    asm volatile("cp.async.commit_group;" ::: "memory");

    // ---- stage Bext once: [3 dz][10 he][34 we] x 64 ci fp16, swizzled rows
    for (int r = tid; r < EXT_ROWS; r += 256) {
        int dz_l = r / 340, rem = r - dz_l * 340;
        int he = rem / 34, we = rem - he * 34;
        const int dz = d + dz_l - 1;
        const int hg = hBase + he - 1;
        const int wg = wBase + we - 1;
        const bool ok = ((unsigned)dz < DD) && ((unsigned)hg < HH) && ((unsigned)wg < WW);
        const float* xp = x + (size_t)dz * HW + hg * WW + wg;
        const uint32_t sw = (uint32_t)(r & 7);
        const uint32_t dbase = smB_u + r * 128;
#pragma unroll
        for (int c = 0; c < 8; ++c) {
            uint32_t pk[4];
#pragma unroll
            for (int j = 0; j < 4; ++j) {
                const int ci = c * 8 + j * 2;
                float v0 = ok ? xp[(size_t)ci * DHW] : 0.0f;
                float v1 = ok ? xp[(size_t)(ci + 1) * DHW] : 0.0f;
                __half2 h2 = __float22half2_rn(make_float2(v0, v1));
                pk[j] = *reinterpret_cast<uint32_t*>(&h2);
            }
            STS128_V(dbase + ((c ^ sw) << 4), pk[0], pk[1], pk[2], pk[3]);
        }
    }

    float acc[4][8][4];
#pragma unroll
    for (int f = 0; f < 4; ++f)
#pragma unroll
        for (int g = 0; g < 8; ++g)
#pragma unroll
            for (int c = 0; c < 4; ++c) acc[f][g][c] = 0.0f;

    for (int tap = 0; tap < 27; ++tap) {
        __syncthreads();   // prev compute done (buf (tap+1)&1 free); Bext visible on tap 0
        if (tap + 1 < 27) stage_A(smA_u, (tap + 1) & 1, tap + 1, coutBase, tid);
        asm volatile("cp.async.commit_group;" ::: "memory");
        asm volatile("cp.async.wait_group 1;" ::: "memory");   // A[tap] ready
        __syncthreads();

        const uint32_t Abase = smA_u + (tap & 1) * SMA_BYTES;
        const int broff = (tap / 9) * 340 + ((tap / 3) % 3) * 34 + (tap % 3);
#pragma unroll
        for (int s = 0; s < 4; ++s) {
            const int col16 = s * 2 + khalf;
            uint32_t a[4][4];
#pragma unroll
            for (int f = 0; f < 4; ++f) {
                ldsm_x4(a[f][0], a[f][1], a[f][2], a[f][3],
                        Abase + rowA[f] * 128 + ((col16 ^ rowA7[f]) << 4));
            }
            uint32_t b[8][2];
#pragma unroll
            for (int g2 = 0; g2 < 4; ++g2) {
                const int brow = browB[g2] + broff;
                ldsm_x4(b[2 * g2][0], b[2 * g2 + 1][0],
                        b[2 * g2][1], b[2 * g2 + 1][1],
                        smB_u + brow * 128 + ((col16 ^ (brow & 7)) << 4));
            }
#pragma unroll
            for (int f = 0; f < 4; ++f)
#pragma unroll
                for (int g = 0; g < 8; ++g) {
                    asm volatile(
                        "mma.sync.aligned.m16n8k16.row.col.f32.f16.f16.f32 "
                        "{%0,%1,%2,%3}, {%4,%5,%6,%7}, {%8,%9}, {%0,%1,%2,%3};"
                        : "+f"(acc[f][g][0]), "+f"(acc[f][g][1]),
                          "+f"(acc[f][g][2]), "+f"(acc[f][g][3])
                        : "r"(a[f][0]), "r"(a[f][1]), "r"(a[f][2]), "r"(a[f][3]),
                          "r"(b[g][0]), "r"(b[g][1]));
                }
        }
    }

    // ---- epilogue: BN + activation + STG (float2)
#pragma unroll
    for (int f = 0; f < 4; ++f)
#pragma unroll
        for (int r = 0; r < 2; ++r) {
            const int cg = coutBase + warpM + 16 * f + 8 * r + mr;
            const float s = gamma[cg] * rsqrtf(var[cg] + EPS);
            const float sh = beta[cg] - mean[cg] * s;
            const int gt = cg >> 6;
            const bool sg = (gt == 1) || (gt == 2);
            float* orow = g_gates + (size_t)cg * DHW + (size_t)d * HW;
#pragma unroll
            for (int g = 0; g < 8; ++g) {
                const int n0 = warpN + 8 * g + 2 * nc;
                const int h2 = n0 >> 5, w2 = n0 & 31;
                float v0 = acc[f][g][2 * r + 0] * s + sh;
                float v1 = acc[f][g][2 * r + 1] * s + sh;
                if (sg) {
                    v0 = 0.5f * fast_tanh(0.5f * v0) + 0.5f;
                    v1 = 0.5f * fast_tanh(0.5f * v1) + 0.5f;
                } else {
                    v0 = fast_tanh(v0);
                    v1 = fast_tanh(v1);
                }
                *reinterpret_cast<float2*>(orow + (hBase + h2) * WW + wBase + w2)
                    = make_float2(v0, v1);
            }
        }
}

// ---------------- SRU scan over depth ----------------
__global__ void sru_scan_kernel(float* __restrict__ out)
{
    const int idx = blockIdx.x * blockDim.x + threadIdx.x;
    if (idx >= CIN * HW) return;
    const int c = idx / HW;
    const int hw = idx % HW;

    const float* pw = g_gates + (size_t)(0 * 64 + c) * DHW + hw;
    const float* pf = g_gates + (size_t)(1 * 64 + c) * DHW + hw;
    const float* pr = g_gates + (size_t)(2 * 64 + c) * DHW + hw;
    const float* px = g_gates + (size_t)(3 * 64 + c) * DHW + hw;
    float* po = out + (size_t)c * DHW + hw;

    float f = pf[0], r = pr[0], xx = px[0];
    float C = 1.0f - f;
    po[0] = r * C + (1.0f - r) * xx;

    for (int dd = 1; dd < DD; ++dd) {
        const int off = dd * HW;
        const float wv = pw[off];
        f = pf[off]; r = pr[off]; xx = px[off];
        C = f * C + (1.0f - f) * wv;
        po[off] = r * C + (1.0f - r) * xx;
    }
}

extern "C" void kernel_launch(void* const* d_in, const int* in_sizes, int n_in,
                              void* d_out, int out_size)
{
    const float* x     = (const float*)d_in[0];
    const float* w     = (const float*)d_in[1];
    const float* gamma = (const float*)d_in[2];
    const float* beta  = (const float*)d_in[3];
    const float* mean  = (const float*)d_in[4];
    const float* var   = (const float*)d_in[5];
    float* out = (float*)d_out;

    repack_kernel<<<64, 256>>>(w);

    cudaFuncSetAttribute(conv_mma_kernel,
                         cudaFuncAttributeMaxDynamicSharedMemorySize, SMEM_TOTAL);
    dim3 grid(36, 31, 2);    // (12 h-tiles x 3 w-tiles), d, cout-groups
    conv_mma_kernel<<<grid, 256, SMEM_TOTAL>>>(x, gamma, beta, mean, var);

    const int scan_threads = 256;
    const int scan_blocks = (CIN * HW + scan_threads - 1) / scan_threads;
    sru_scan_kernel<<<scan_blocks, scan_threads>>>(out);
}

// round 6
// speedup vs baseline: 8.8805x; 1.1003x over previous
#include <cuda_runtime.h>
#include <cuda_fp16.h>
#include <cstdint>
#include <math.h>

#define CIN 64
#define COUT 256
#define DD 31
#define HH 96
#define WW 96
#define HW (HH*WW)
#define DHW (DD*HW)
#define EPS 1e-5f

#define BH 8
#define BW 32

// padded transposed x: [33][98][104][64] fp16, swizzle baked (key = w&7)
#define XT_D 33
#define XT_H 98
#define XT_W 104
#define XT_ROWS (XT_D*XT_H*XT_W)
__device__ __half g_xt[(size_t)XT_ROWS * 64];

__device__ float  g_gates[(size_t)COUT * DHW];   // activated gates [cout][d][h][w]
__device__ __half g_wth[27 * COUT * CIN];        // [tap][cout][cin] fp16, swizzle baked (key = cout&7)

// smem layout: A double buffer 2x16KB, then B region
#define SMA_BYTES 16384
#define SMB_OFF (2*SMA_BYTES)
#define B_ROW_BASE 7
#define B_RUN_STRIDE 40
#define B_ROWS (B_ROW_BASE + 29*B_RUN_STRIDE + 34)   // 1201
#define SMEM_TOTAL (SMB_OFF + B_ROWS*128)            // 186496

__device__ __forceinline__ uint32_t cvta_s(const void* p) {
    uint32_t a;
    asm("{ .reg .u64 t; cvta.to.shared.u64 t, %1; cvt.u32.u64 %0, t; }" : "=r"(a) : "l"(p));
    return a;
}
__device__ __forceinline__ float fast_tanh(float x) {
    float y; asm("tanh.approx.f32 %0, %1;" : "=f"(y) : "f"(x)); return y;
}
__device__ __forceinline__ void ldsm_x4(uint32_t& r0, uint32_t& r1, uint32_t& r2, uint32_t& r3,
                                        uint32_t addr) {
    asm volatile("ldmatrix.sync.aligned.m8n8.x4.shared.b16 {%0,%1,%2,%3}, [%4];"
        : "=r"(r0), "=r"(r1), "=r"(r2), "=r"(r3) : "r"(addr));
}
#define MBAR_INIT(mbar, count) \
    asm volatile("mbarrier.init.shared.b64 [%0], %1;" :: "r"((uint32_t)(mbar)), "r"((uint32_t)(count)) : "memory")
#define MBAR_EXPECT_TX(mbar, bytes) \
    asm volatile("mbarrier.arrive.expect_tx.shared.b64 _, [%0], %1;" \
        :: "r"((uint32_t)(mbar)), "r"((uint32_t)(bytes)) : "memory")
#define MBAR_WAIT(mbar, parity) do { \
    uint32_t _m = (uint32_t)(mbar); uint32_t _p = (uint32_t)(parity); uint32_t _done; \
    asm volatile("{\n\t.reg .pred p;\n\tmbarrier.try_wait.parity.acquire.cta.shared::cta.b64 p, [%1], %2;\n\tselp.b32 %0, 1, 0, p;\n\t}" \
        : "=r"(_done) : "r"(_m), "r"(_p) : "memory"); \
    if (!_done) { \
        asm volatile("{\n\t.reg .pred P1;\n\tWL_%=:\n\tmbarrier.try_wait.parity.acquire.cta.shared::cta.b64 P1, [%0], %1, 0x989680;\n\t@P1 bra.uni WD_%=;\n\tbra.uni WL_%=;\n\tWD_%=:\n\t}" \
            :: "r"(_m), "r"(_p) : "memory"); \
    } } while (0)
#define BULK_G2S(dst, src, bytes, mbar) \
    asm volatile("cp.async.bulk.shared::cluster.global.mbarrier::complete_tx::bytes [%0], [%1], %2, [%3];" \
        :: "r"((uint32_t)(dst)), "l"(src), "r"((uint32_t)(bytes)), "r"((uint32_t)(mbar)) : "memory")

// ---------------- pre-pass kernels ----------------
__global__ void zero_xt_kernel() {
    size_t i = (size_t)blockIdx.x * blockDim.x + threadIdx.x;
    float4* p = reinterpret_cast<float4*>(g_xt);
    if (i < ((size_t)XT_ROWS * 128) / 16) p[i] = make_float4(0.f, 0.f, 0.f, 0.f);
}

// x[ci][d][h][w] f32 -> g_xt[(d+1)][(h+1)][(w+1)][ci] fp16, chunks swizzled by (w&7)
__global__ void transpose_x_kernel(const float* __restrict__ x) {
    const int d = blockIdx.y, h = blockIdx.x;
    const int w = threadIdx.x;
    if (w >= WW) return;
    const float* src = x + (size_t)d * HW + h * WW + w;
    uint32_t pk[32];
#pragma unroll
    for (int j = 0; j < 32; ++j) {
        float v0 = src[(size_t)(2 * j) * DHW];
        float v1 = src[(size_t)(2 * j + 1) * DHW];
        __half2 h2 = __float22half2_rn(make_float2(v0, v1));
        pk[j] = *reinterpret_cast<uint32_t*>(&h2);
    }
    char* dst = (char*)g_xt + ((size_t)((d + 1) * XT_H + (h + 1)) * XT_W + (w + 1)) * 128;
    const int key = w & 7;
#pragma unroll
    for (int c = 0; c < 8; ++c) {
        uint4 q = make_uint4(pk[c * 4], pk[c * 4 + 1], pk[c * 4 + 2], pk[c * 4 + 3]);
        *reinterpret_cast<uint4*>(dst + ((c ^ key) << 4)) = q;
    }
}

// w[cout][cin][27] -> g_wth[tap][cout][...swizzled cin...]
__global__ void repack_kernel(const float* __restrict__ w) {
    int id = blockIdx.x * blockDim.x + threadIdx.x;
    if (id >= COUT * CIN) return;
    int cout = id >> 6, cin = id & 63;
    const float* src = w + (size_t)id * 27;
    const int c = cin >> 3, key = cout & 7;
    const int pos = ((c ^ key) << 3) + (cin & 7);
#pragma unroll
    for (int t = 0; t < 27; ++t)
        g_wth[((size_t)t * COUT + cout) * 64 + pos] = __float2half_rn(src[t]);
}

// ---------------- conv + BN + activation ----------------
__global__ __launch_bounds__(256, 1)
void conv_mma_kernel(const float* __restrict__ gamma, const float* __restrict__ beta,
                     const float* __restrict__ mean, const float* __restrict__ var)
{
    extern __shared__ __align__(128) char smem[];
    __shared__ __align__(8) uint64_t mbars[3];   // A0, A1, B
    const uint32_t smA_u = cvta_s(smem);
    const uint32_t smB_u = smA_u + SMB_OFF;
    const uint32_t mbA0 = cvta_s(&mbars[0]);
    const uint32_t mbA1 = cvta_s(&mbars[1]);
    const uint32_t mbB  = cvta_s(&mbars[2]);

    const int tid = threadIdx.x, wid = tid >> 5, lane = tid & 31;
    const int d = blockIdx.y;
    const int coutBase = blockIdx.z * 128;
    const int hBase = (blockIdx.x / 3) * BH, wBase = (blockIdx.x % 3) * BW;

    const int warpM = (wid >> 2) * 64, warpN = (wid & 3) * 64;
    const int mr = lane >> 2, nc = lane & 3;
    const int matsel = lane >> 3, rl = lane & 7;
    const int mhalf = matsel & 1, khalf = matsel >> 1;

    int rowA[4], rowA7[4];
#pragma unroll
    for (int f = 0; f < 4; ++f) {
        rowA[f] = warpM + 16 * f + mhalf * 8 + rl;
        rowA7[f] = rowA[f] & 7;
    }
    int browB[4];
#pragma unroll
    for (int g2 = 0; g2 < 4; ++g2) {
        int n = warpN + g2 * 16 + mhalf * 8 + rl;
        browB[g2] = B_ROW_BASE + (n >> 5) * B_RUN_STRIDE + (n & 31);
    }

    if (tid == 0) { MBAR_INIT(mbA0, 1); MBAR_INIT(mbA1, 1); MBAR_INIT(mbB, 1); }
    __syncthreads();

    if (tid == 0) {
        // ---- B: 30 bulk runs of 34 rows x 128B
        MBAR_EXPECT_TX(mbB, 30u * 4352u);
#pragma unroll
        for (int dzl = 0; dzl < 3; ++dzl) {
            const int dz = d + dzl;   // padded plane index = dz (since dz-1+1)
            for (int he = 0; he < 10; ++he) {
                const int hp = hBase + he;   // padded h index
                const char* src = (const char*)g_xt
                    + ((size_t)(dz * XT_H + hp) * XT_W + wBase) * 128;
                const int ri = dzl * 10 + he;
                BULK_G2S(smB_u + (B_ROW_BASE + ri * B_RUN_STRIDE) * 128, src, 4352u, mbB);
            }
        }
        // ---- A tap 0
        MBAR_EXPECT_TX(mbA0, SMA_BYTES);
        BULK_G2S(smA_u, (const char*)g_wth + (size_t)coutBase * 128, SMA_BYTES, mbA0);
    }

    float acc[4][8][4];
#pragma unroll
    for (int f = 0; f < 4; ++f)
#pragma unroll
        for (int g = 0; g < 8; ++g)
#pragma unroll
            for (int c = 0; c < 4; ++c) acc[f][g][c] = 0.0f;

    MBAR_WAIT(mbB, 0);

    for (int tap = 0; tap < 27; ++tap) {
        if (tap > 0) __syncthreads();   // all warps done with buffer (tap+1)&1
        if (tid == 0 && tap + 1 < 27) {
            const uint32_t mb = ((tap + 1) & 1) ? mbA1 : mbA0;
            MBAR_EXPECT_TX(mb, SMA_BYTES);
            BULK_G2S(smA_u + ((tap + 1) & 1) * SMA_BYTES,
                     (const char*)g_wth + ((size_t)(tap + 1) * COUT + coutBase) * 128,
                     SMA_BYTES, mb);
        }
        MBAR_WAIT((tap & 1) ? mbA1 : mbA0, (tap >> 1) & 1);

        const uint32_t Abase = smA_u + (tap & 1) * SMA_BYTES;
        const int kd = tap / 9, kh = (tap / 3) % 3, kw = tap % 3;
        const int broff = kd * (10 * B_RUN_STRIDE) + kh * B_RUN_STRIDE + kw;
#pragma unroll
        for (int s = 0; s < 4; ++s) {
            const int col16 = s * 2 + khalf;
            uint32_t a[4][4];
#pragma unroll
            for (int f = 0; f < 4; ++f) {
                ldsm_x4(a[f][0], a[f][1], a[f][2], a[f][3],
                        Abase + rowA[f] * 128 + ((col16 ^ rowA7[f]) << 4));
            }
            uint32_t b[8][2];
#pragma unroll
            for (int g2 = 0; g2 < 4; ++g2) {
                const int brow = browB[g2] + broff;
                ldsm_x4(b[2 * g2][0], b[2 * g2 + 1][0],
                        b[2 * g2][1], b[2 * g2 + 1][1],
                        smB_u + brow * 128 + ((col16 ^ (brow & 7)) << 4));
            }
#pragma unroll
            for (int f = 0; f < 4; ++f)
#pragma unroll
                for (int g = 0; g < 8; ++g) {
                    asm volatile(
                        "mma.sync.aligned.m16n8k16.row.col.f32.f16.f16.f32 "
                        "{%0,%1,%2,%3}, {%4,%5,%6,%7}, {%8,%9}, {%0,%1,%2,%3};"
                        : "+f"(acc[f][g][0]), "+f"(acc[f][g][1]),
                          "+f"(acc[f][g][2]), "+f"(acc[f][g][3])
                        : "r"(a[f][0]), "r"(a[f][1]), "r"(a[f][2]), "r"(a[f][3]),
                          "r"(b[g][0]), "r"(b[g][1]));
                }
        }
    }

    // ---- epilogue: BN + activation + STG (float2)
#pragma unroll
    for (int f = 0; f < 4; ++f)
#pragma unroll
        for (int r = 0; r < 2; ++r) {
            const int cg = coutBase + warpM + 16 * f + 8 * r + mr;
            const float s = gamma[cg] * rsqrtf(var[cg] + EPS);
            const float sh = beta[cg] - mean[cg] * s;
            const int gt = cg >> 6;
            const bool sg = (gt == 1) || (gt == 2);
            float* orow = g_gates + (size_t)cg * DHW + (size_t)d * HW;
#pragma unroll
            for (int g = 0; g < 8; ++g) {
                const int n0 = warpN + 8 * g + 2 * nc;
                const int h2 = n0 >> 5, w2 = n0 & 31;
                float v0 = acc[f][g][2 * r + 0] * s + sh;
                float v1 = acc[f][g][2 * r + 1] * s + sh;
                if (sg) {
                    v0 = 0.5f * fast_tanh(0.5f * v0) + 0.5f;
                    v1 = 0.5f * fast_tanh(0.5f * v1) + 0.5f;
                } else {
                    v0 = fast_tanh(v0);
                    v1 = fast_tanh(v1);
                }
                *reinterpret_cast<float2*>(orow + (hBase + h2) * WW + wBase + w2)
                    = make_float2(v0, v1);
            }
        }
}

// ---------------- SRU scan over depth ----------------
__global__ void sru_scan_kernel(float* __restrict__ out)
{
    const int idx = blockIdx.x * blockDim.x + threadIdx.x;
    if (idx >= CIN * HW) return;
    const int c = idx / HW;
    const int hw = idx % HW;

    const float* pw = g_gates + (size_t)(0 * 64 + c) * DHW + hw;
    const float* pf = g_gates + (size_t)(1 * 64 + c) * DHW + hw;
    const float* pr = g_gates + (size_t)(2 * 64 + c) * DHW + hw;
    const float* px = g_gates + (size_t)(3 * 64 + c) * DHW + hw;
    float* po = out + (size_t)c * DHW + hw;

    float f = pf[0], r = pr[0], xx = px[0];
    float C = 1.0f - f;
    po[0] = r * C + (1.0f - r) * xx;

    for (int dd = 1; dd < DD; ++dd) {
        const int off = dd * HW;
        const float wv = pw[off];
        f = pf[off]; r = pr[off]; xx = px[off];
        C = f * C + (1.0f - f) * wv;
        po[off] = r * C + (1.0f - r) * xx;
    }
}

extern "C" void kernel_launch(void* const* d_in, const int* in_sizes, int n_in,
                              void* d_out, int out_size)
{
    const float* x     = (const float*)d_in[0];
    const float* w     = (const float*)d_in[1];
    const float* gamma = (const float*)d_in[2];
    const float* beta  = (const float*)d_in[3];
    const float* mean  = (const float*)d_in[4];
    const float* var   = (const float*)d_in[5];
    float* out = (float*)d_out;

    const size_t xt_vec = ((size_t)XT_ROWS * 128) / 16;
    zero_xt_kernel<<<(int)((xt_vec + 255) / 256), 256>>>();
    transpose_x_kernel<<<dim3(HH, DD), 128>>>(x);
    repack_kernel<<<64, 256>>>(w);

    cudaFuncSetAttribute(conv_mma_kernel,
                         cudaFuncAttributeMaxDynamicSharedMemorySize, SMEM_TOTAL);
    dim3 grid(36, 31, 2);    // (12 h-tiles x 3 w-tiles), d, cout-groups
    conv_mma_kernel<<<grid, 256, SMEM_TOTAL>>>(gamma, beta, mean, var);

    const int scan_threads = 256;
    const int scan_blocks = (CIN * HW + scan_threads - 1) / scan_threads;
    sru_scan_kernel<<<scan_blocks, scan_threads>>>(out);
}